// round 10
// baseline (speedup 1.0000x reference)
#include <cuda_runtime.h>
#include <cuda_bf16.h>
#include <cstdint>

// MultiHeadAttention: B=2, N=4096, E=512, H=8, D=64
// Output = concat(flatten(out[B,N,E]), flatten(attn[B,H,N,N]))

#define NH   8
#define HD   64
#define SEQ  4096
#define EMB  512
#define NB   2
#define MTOT (NB * SEQ)   // 8192
#define BHT  (NB * NH)    // 16

// scratch (device globals — allocation inside kernel_launch is forbidden)
__device__ __align__(16) __nv_bfloat16 g_qh[(size_t)BHT * SEQ * HD];
__device__ __align__(16) __nv_bfloat16 g_ql[(size_t)BHT * SEQ * HD];
__device__ __align__(16) __nv_bfloat16 g_kh[(size_t)BHT * SEQ * HD];
__device__ __align__(16) __nv_bfloat16 g_kl[(size_t)BHT * SEQ * HD];
__device__ __align__(16) __nv_bfloat16 g_vth[(size_t)BHT * HD * SEQ];  // V^T: (bh,d,n)
__device__ __align__(16) __nv_bfloat16 g_vtl[(size_t)BHT * HD * SEQ];
__device__ __align__(16) __nv_bfloat16 g_oh[(size_t)MTOT * EMB];       // O: (B,N,E)
__device__ __align__(16) __nv_bfloat16 g_ol[(size_t)MTOT * EMB];
__device__ __align__(16) __nv_bfloat16 g_xh[(size_t)MTOT * EMB];       // staged X hi/lo
__device__ __align__(16) __nv_bfloat16 g_xl[(size_t)MTOT * EMB];
__device__ __align__(16) __nv_bfloat16 g_wh[(size_t)EMB * EMB];        // staged W hi/lo
__device__ __align__(16) __nv_bfloat16 g_wl[(size_t)EMB * EMB];
__device__ float g_m[BHT * SEQ];
__device__ float g_l[BHT * SEQ];

// ===========================================================================
// helpers
// ===========================================================================
__device__ __forceinline__ uint32_t pack2bf16(float lo, float hi) {
    return ((uint32_t)__bfloat16_as_ushort(__float2bfloat16(hi)) << 16) |
           (uint32_t)__bfloat16_as_ushort(__float2bfloat16(lo));
}
__device__ __forceinline__ void split_hl(float x, float& h, float& l) {
    __nv_bfloat16 b = __float2bfloat16(x);
    h = __bfloat162float(b);
    l = x - h;
}
__device__ __forceinline__ void pack_hl2(float a, float b, uint32_t& hw, uint32_t& lw) {
    float ah, al, bh, bl;
    split_hl(a, ah, al);
    split_hl(b, bh, bl);
    hw = pack2bf16(ah, bh);
    lw = pack2bf16(al, bl);
}

__device__ __forceinline__ void mma16816(float* c, const uint32_t* a, const uint32_t* b) {
    asm volatile(
        "mma.sync.aligned.m16n8k16.row.col.f32.bf16.bf16.f32 "
        "{%0,%1,%2,%3}, {%4,%5,%6,%7}, {%8,%9}, {%0,%1,%2,%3};"
        : "+f"(c[0]), "+f"(c[1]), "+f"(c[2]), "+f"(c[3])
        : "r"(a[0]), "r"(a[1]), "r"(a[2]), "r"(a[3]), "r"(b[0]), "r"(b[1]));
}
__device__ __forceinline__ void ldm_x4(uint32_t* r, uint32_t addr) {
    asm volatile("ldmatrix.sync.aligned.m8n8.x4.shared.b16 {%0,%1,%2,%3}, [%4];"
        : "=r"(r[0]), "=r"(r[1]), "=r"(r[2]), "=r"(r[3]) : "r"(addr));
}

__device__ __forceinline__ uint32_t smem_u32(const void* p) {
    uint32_t a;
    asm("{ .reg .u64 t; cvta.to.shared.u64 t, %1; cvt.u32.u64 %0, t; }"
        : "=r"(a) : "l"(p));
    return a;
}
__device__ __forceinline__ void cp16(uint32_t dst, const void* src) {
    asm volatile("cp.async.cg.shared.global [%0], [%1], 16;" :: "r"(dst), "l"(src));
}
#define CP_COMMIT() asm volatile("cp.async.commit_group;")
#define CP_WAIT0()  asm volatile("cp.async.wait_group 0;")
#define CP_WAIT1()  asm volatile("cp.async.wait_group 1;")

// ldmatrix per-thread element offsets within a padded-72 tile:
//   A x4 (m16 x k16): row = rbase + (l & 15), kcol = (l >> 4) * 8
//   B x4 (two n8 blocks x k16): row = (l & 7) + ((l >> 4) << 3), kcol = ((l >> 3) & 1) * 8
#define A_OFF(rbase, l) ((((rbase) + ((l) & 15)) * 72 + (((l) >> 4) << 3)))
#define B_OFF(l)        (((((l) & 7) + (((l) >> 4) << 3)) * 72 + ((((l) >> 3) & 1) << 3)))

// ===========================================================================
// fp32 -> bf16 hi/lo conversion (vectorized)
// ===========================================================================
__global__ __launch_bounds__(256) void cvt_hl_kernel(
    const float* __restrict__ src, __nv_bfloat16* __restrict__ h,
    __nv_bfloat16* __restrict__ l, int n4)
{
    int i = blockIdx.x * 256 + threadIdx.x;
    if (i < n4) {
        float4 f = ((const float4*)src)[i];
        uint32_t h01, l01, h23, l23;
        pack_hl2(f.x, f.y, h01, l01);
        pack_hl2(f.z, f.w, h23, l23);
        ((uint2*)h)[i] = make_uint2(h01, h23);
        ((uint2*)l)[i] = make_uint2(l01, l23);
    }
}

// ===========================================================================
// Tensor projection GEMM: C = A @ W^T (+bias, scale) via hi/lo bf16 mma.
// mode 0: Q -> g_qh/g_ql scatter (B,H,N,D), scale=0.125
// mode 1: K -> g_kh/g_kl scatter (B,H,N,D)
// mode 2: out -> fout fp32 (M,E)
// mode 3: V -> g_vth/g_vtl transposed scatter (B,H,D,N)
// CTA 128 thr, tile 64x64, BK=64; warp = 16 rows x 64 cols.
// ===========================================================================
__global__ __launch_bounds__(128) void gemm_proj(
    const float* __restrict__ bias, float scale, int mode,
    float* __restrict__ fout)
{
    __shared__ __align__(16) __nv_bfloat16 sAB[4 * 64 * 72];
    __nv_bfloat16* sAh = sAB;
    __nv_bfloat16* sAl = sAB + 4608;
    __nv_bfloat16* sBh = sAB + 9216;
    __nv_bfloat16* sBl = sAB + 13824;

    const int t = threadIdx.x, w = t >> 5, l = t & 31;
    const int row0 = blockIdx.x * 64, col0 = blockIdx.y * 64;
    const int rA = w*16 + (l >> 2);
    const int koffb = (l & 3) * 2;

    const __nv_bfloat16* Ah = (mode == 2) ? g_oh : g_xh;
    const __nv_bfloat16* Al = (mode == 2) ? g_ol : g_xl;

    const uint32_t sb   = smem_u32(sAB);
    const uint32_t aho  = sb + (0     + A_OFF(w*16, l)) * 2;
    const uint32_t alo  = sb + (4608  + A_OFF(w*16, l)) * 2;
    const uint32_t bho  = sb + (9216  + B_OFF(l)) * 2;
    const uint32_t blo  = sb + (13824 + B_OFF(l)) * 2;

    float acc[8][4];
#pragma unroll
    for (int nt = 0; nt < 8; nt++)
#pragma unroll
        for (int c = 0; c < 4; c++) acc[nt][c] = 0.f;

    for (int kb = 0; kb < EMB/64; kb++) {
        __syncthreads();
#pragma unroll
        for (int it = 0; it < 4; it++) {
            int j = it*128 + t, row = j >> 3, i = j & 7;
            size_t ga = (size_t)(row0 + row) * EMB + kb*64 + i*8;
            size_t gb = (size_t)(col0 + row) * EMB + kb*64 + i*8;
            *(uint4*)&sAh[row*72 + i*8] = *(const uint4*)(Ah + ga);
            *(uint4*)&sAl[row*72 + i*8] = *(const uint4*)(Al + ga);
            *(uint4*)&sBh[row*72 + i*8] = *(const uint4*)(g_wh + gb);
            *(uint4*)&sBl[row*72 + i*8] = *(const uint4*)(g_wl + gb);
        }
        __syncthreads();

#pragma unroll
        for (int ks = 0; ks < 4; ks++) {
            const int kbo = ks*16*2;
            uint32_t ah[4], al[4];
            ldm_x4(ah, aho + kbo);
            ldm_x4(al, alo + kbo);
#pragma unroll
            for (int np = 0; np < 4; np++) {
                uint32_t bh4[4], bl4[4];
                ldm_x4(bh4, bho + (np*16*72)*2 + kbo);
                ldm_x4(bl4, blo + (np*16*72)*2 + kbo);
                mma16816(acc[2*np],   ah, bh4);
                mma16816(acc[2*np],   ah, bl4);
                mma16816(acc[2*np],   al, bh4);
                mma16816(acc[2*np+1], ah, bh4+2);
                mma16816(acc[2*np+1], ah, bl4+2);
                mma16816(acc[2*np+1], al, bh4+2);
            }
        }
    }

    const int gm1 = row0 + rA, gm2 = gm1 + 8;
    if (mode == 2) {
#pragma unroll
        for (int nt = 0; nt < 8; nt++) {
            const int dd = nt*8 + koffb;
            float b0 = bias[col0 + dd], b1 = bias[col0 + dd + 1];
            *(float2*)&fout[(size_t)gm1*EMB + col0 + dd] =
                make_float2(acc[nt][0] + b0, acc[nt][1] + b1);
            *(float2*)&fout[(size_t)gm2*EMB + col0 + dd] =
                make_float2(acc[nt][2] + b0, acc[nt][3] + b1);
        }
    } else if (mode == 3) {
        // transpose epilogue: stage fp32 into smem, write V^T hi/lo (B,H,D,N)
        float* St = (float*)sAB;   // 64 x 65 floats = 16.6KB < sAh+sAl (18.4KB)
        __syncthreads();
#pragma unroll
        for (int nt = 0; nt < 8; nt++) {
            const int dd = nt*8 + koffb;
            float b0 = bias[col0 + dd], b1 = bias[col0 + dd + 1];
            St[rA*65 + dd]       = acc[nt][0] + b0;
            St[rA*65 + dd + 1]   = acc[nt][1] + b1;
            St[(rA+8)*65 + dd]   = acc[nt][2] + b0;
            St[(rA+8)*65 + dd+1] = acc[nt][3] + b1;
        }
        __syncthreads();
        const int h  = col0 >> 6;
        const int bb = row0 >> 12;
        const int n0 = row0 & (SEQ - 1);
        const int d  = t >> 1;
        const int j0 = (t & 1) * 32;
        uint32_t ph[16], pl[16];
#pragma unroll
        for (int jj = 0; jj < 16; jj++)
            pack_hl2(St[(j0 + 2*jj)*65 + d], St[(j0 + 2*jj + 1)*65 + d], ph[jj], pl[jj]);
        size_t vb = ((size_t)((bb*NH + h)*HD + d)) * SEQ + n0 + j0;
#pragma unroll
        for (int q = 0; q < 4; q++) {
            *(uint4*)&g_vth[vb + q*8] = ((uint4*)ph)[q];
            *(uint4*)&g_vtl[vb + q*8] = ((uint4*)pl)[q];
        }
    } else {
        __nv_bfloat16* oh = (mode == 0) ? g_qh : g_kh;
        __nv_bfloat16* ol = (mode == 0) ? g_ql : g_kl;
        const int h = col0 >> 6;
        const int bb1 = gm1 >> 12, n1 = gm1 & (SEQ-1);
        const int bb2 = gm2 >> 12, n2 = gm2 & (SEQ-1);
#pragma unroll
        for (int nt = 0; nt < 8; nt++) {
            const int dd = nt*8 + koffb;
            float b0 = bias[col0 + dd], b1 = bias[col0 + dd + 1];
            uint32_t hw, lw;
            pack_hl2((acc[nt][0] + b0) * scale, (acc[nt][1] + b1) * scale, hw, lw);
            size_t base1 = ((size_t)((bb1*NH + h)*SEQ + n1)) * HD + dd;
            *(uint32_t*)&oh[base1] = hw;
            *(uint32_t*)&ol[base1] = lw;
            pack_hl2((acc[nt][2] + b0) * scale, (acc[nt][3] + b1) * scale, hw, lw);
            size_t base2 = ((size_t)((bb2*NH + h)*SEQ + n2)) * HD + dd;
            *(uint32_t*)&oh[base2] = hw;
            *(uint32_t*)&ol[base2] = lw;
        }
    }
}

// ===========================================================================
// Scores via mma.sync + ldmatrix + cp.async double-buffered K tiles (KT=64).
// CTA = 64 q-rows; 4 warps, warp = 16 rows x 64 keys per iter.
// ===========================================================================
#define SOQH 0
#define SOQL 4608
#define SOKH 9216
#define SOKL 18432
#define S_SMEM_BYTES (27648 * 2)

__global__ __launch_bounds__(128) void attn_scores_mma(float* __restrict__ attn)
{
    extern __shared__ __align__(16) __nv_bfloat16 sm[];
    const uint32_t sb = smem_u32(sm);
    const int t = threadIdx.x, w = t >> 5, l = t & 31;
    const int bh = blockIdx.y, q0 = blockIdx.x * 64;

    // Q tile (64 x 64), padded stride 72
#pragma unroll
    for (int it = 0; it < 4; it++) {
        int j = it*128 + t, row = j >> 3, i = j & 7;
        size_t gsrc = ((size_t)(bh*SEQ + q0 + row)) * HD + i*8;
        *(uint4*)&sm[SOQH + row*72 + i*8] = *(const uint4*)(g_qh + gsrc);
        *(uint4*)&sm[SOQL + row*72 + i*8] = *(const uint4*)(g_ql + gsrc);
    }

    const int rA   = w*16 + (l >> 2);
    const int gr1  = q0 + rA, gr2 = gr1 + 8;
    const size_t ar1 = ((size_t)bh*SEQ + gr1) * SEQ;
    const size_t ar2 = ((size_t)bh*SEQ + gr2) * SEQ;
    const int koffb = (l & 3) * 2;

    const uint32_t aho = sb + (SOQH + A_OFF(w*16, l)) * 2;
    const uint32_t alo = sb + (SOQL + A_OFF(w*16, l)) * 2;
    const uint32_t bof = B_OFF(l);

    float m1 = -1e30f, l1 = 0.f, m2 = -1e30f, l2 = 0.f;

    // prefetch K tile 0 into stage 0
    {
#pragma unroll
        for (int it = 0; it < 4; it++) {
            int j = it*128 + t, row = j >> 3, i = j & 7;
            size_t gsrc = ((size_t)(bh*SEQ + row)) * HD + i*8;
            cp16(sb + (SOKH + row*72 + i*8)*2, g_kh + gsrc);
            cp16(sb + (SOKL + row*72 + i*8)*2, g_kl + gsrc);
        }
        CP_COMMIT();
    }

    for (int kt = 0; kt < SEQ/64; kt++) {
        const int cur = kt & 1;
        if (kt + 1 < SEQ/64) {
            const int nxt = cur ^ 1;
#pragma unroll
            for (int it = 0; it < 4; it++) {
                int j = it*128 + t, row = j >> 3, i = j & 7;
                size_t gsrc = ((size_t)(bh*SEQ + (kt+1)*64 + row)) * HD + i*8;
                cp16(sb + (SOKH + nxt*4608 + row*72 + i*8)*2, g_kh + gsrc);
                cp16(sb + (SOKL + nxt*4608 + row*72 + i*8)*2, g_kl + gsrc);
            }
            CP_COMMIT();
            CP_WAIT1();
        } else {
            CP_WAIT0();
        }
        __syncthreads();

        float acc[8][4];
#pragma unroll
        for (int nt = 0; nt < 8; nt++)
#pragma unroll
            for (int c = 0; c < 4; c++) acc[nt][c] = 0.f;

        const uint32_t kho = sb + (SOKH + cur*4608 + bof) * 2;
        const uint32_t klo = sb + (SOKL + cur*4608 + bof) * 2;
#pragma unroll
        for (int ks = 0; ks < 4; ks++) {
            const int kbo = ks*16*2;
            uint32_t ah[4], al[4];
            ldm_x4(ah, aho + kbo);
            ldm_x4(al, alo + kbo);
#pragma unroll
            for (int np = 0; np < 4; np++) {
                uint32_t bh4[4], bl4[4];
                ldm_x4(bh4, kho + (np*16*72)*2 + kbo);
                ldm_x4(bl4, klo + (np*16*72)*2 + kbo);
                mma16816(acc[2*np],   ah, bh4);
                mma16816(acc[2*np],   ah, bl4);
                mma16816(acc[2*np],   al, bh4);
                mma16816(acc[2*np+1], ah, bh4+2);
                mma16816(acc[2*np+1], ah, bl4+2);
                mma16816(acc[2*np+1], al, bh4+2);
            }
        }

        // epilogue: store raw scores + online m/l
        float vmax1 = -1e30f, vmax2 = -1e30f;
#pragma unroll
        for (int nt = 0; nt < 8; nt++) {
            vmax1 = fmaxf(vmax1, fmaxf(acc[nt][0], acc[nt][1]));
            vmax2 = fmaxf(vmax2, fmaxf(acc[nt][2], acc[nt][3]));
            const int col = kt*64 + nt*8 + koffb;
            *(float2*)&attn[ar1 + col] = make_float2(acc[nt][0], acc[nt][1]);
            *(float2*)&attn[ar2 + col] = make_float2(acc[nt][2], acc[nt][3]);
        }
        vmax1 = fmaxf(vmax1, __shfl_xor_sync(0xffffffffu, vmax1, 1));
        vmax1 = fmaxf(vmax1, __shfl_xor_sync(0xffffffffu, vmax1, 2));
        vmax2 = fmaxf(vmax2, __shfl_xor_sync(0xffffffffu, vmax2, 1));
        vmax2 = fmaxf(vmax2, __shfl_xor_sync(0xffffffffu, vmax2, 2));

        const float mn1 = fmaxf(m1, vmax1), mn2 = fmaxf(m2, vmax2);
        float es1 = 0.f, es2 = 0.f;
#pragma unroll
        for (int nt = 0; nt < 8; nt++) {
            es1 += __expf(acc[nt][0] - mn1) + __expf(acc[nt][1] - mn1);
            es2 += __expf(acc[nt][2] - mn2) + __expf(acc[nt][3] - mn2);
        }
        es1 += __shfl_xor_sync(0xffffffffu, es1, 1);
        es1 += __shfl_xor_sync(0xffffffffu, es1, 2);
        es2 += __shfl_xor_sync(0xffffffffu, es2, 1);
        es2 += __shfl_xor_sync(0xffffffffu, es2, 2);

        l1 = l1 * __expf(m1 - mn1) + es1;  m1 = mn1;
        l2 = l2 * __expf(m2 - mn2) + es2;  m2 = mn2;

        __syncthreads();
    }

    if ((l & 3) == 0) {
        g_m[bh*SEQ + gr1] = m1;  g_l[bh*SEQ + gr1] = l1;
        g_m[bh*SEQ + gr2] = m2;  g_l[bh*SEQ + gr2] = l2;
    }
}

// ===========================================================================
// AV via mma.sync + ldmatrix + cp.async double-buffered V tiles (KT=64).
// Reads raw scores, normalizes, writes probs back (final attn), O = P @ V,
// stores O bf16 hi/lo in (B,N,E).
// ===========================================================================
__global__ __launch_bounds__(128) void attn_av_mma(float* __restrict__ attn)
{
    __shared__ __align__(16) __nv_bfloat16 sm[18432];
    const uint32_t sb = smem_u32(sm);
    const int t = threadIdx.x, w = t >> 5, l = t & 31;
    const int bh = blockIdx.y, q0 = blockIdx.x * 64;

    const int rA  = w*16 + (l >> 2);
    const int gr1 = q0 + rA, gr2 = gr1 + 8;
    const size_t ar1 = ((size_t)bh*SEQ + gr1) * SEQ;
    const size_t ar2 = ((size_t)bh*SEQ + gr2) * SEQ;
    const int koffb = (l & 3) * 2;
    const uint32_t bof = B_OFF(l);

    const float m1  = g_m[bh*SEQ + gr1];
    const float li1 = 1.0f / g_l[bh*SEQ + gr1];
    const float m2  = g_m[bh*SEQ + gr2];
    const float li2 = 1.0f / g_l[bh*SEQ + gr2];

    float acc[8][4];
#pragma unroll
    for (int nt = 0; nt < 8; nt++)
#pragma unroll
        for (int c = 0; c < 4; c++) acc[nt][c] = 0.f;

    // V stage layout: Vh at stage*4608, Vl at 9216 + stage*4608
    {
#pragma unroll
        for (int it = 0; it < 4; it++) {
            int j = it*128 + t, d = j >> 3, i = j & 7;
            size_t gsrc = ((size_t)(bh*HD + d)) * SEQ + i*8;
            cp16(sb + (d*72 + i*8)*2, g_vth + gsrc);
            cp16(sb + (9216 + d*72 + i*8)*2, g_vtl + gsrc);
        }
        CP_COMMIT();
    }

    for (int kt = 0; kt < SEQ/64; kt++) {
        const int cur = kt & 1;
        if (kt + 1 < SEQ/64) {
            const int nxt = cur ^ 1;
#pragma unroll
            for (int it = 0; it < 4; it++) {
                int j = it*128 + t, d = j >> 3, i = j & 7;
                size_t gsrc = ((size_t)(bh*HD + d)) * SEQ + (kt+1)*64 + i*8;
                cp16(sb + (nxt*4608 + d*72 + i*8)*2, g_vth + gsrc);
                cp16(sb + (9216 + nxt*4608 + d*72 + i*8)*2, g_vtl + gsrc);
            }
            CP_COMMIT();
            CP_WAIT1();
        } else {
            CP_WAIT0();
        }
        __syncthreads();

        const uint32_t vho = sb + (cur*4608 + bof) * 2;
        const uint32_t vlo = sb + (9216 + cur*4608 + bof) * 2;
#pragma unroll
        for (int ks = 0; ks < 4; ks++) {
            const size_t kc = (size_t)kt*64 + ks*16 + koffb;
            float2 s0 = *(float2*)&attn[ar1 + kc];
            float2 s1 = *(float2*)&attn[ar2 + kc];
            float2 s2 = *(float2*)&attn[ar1 + kc + 8];
            float2 s3 = *(float2*)&attn[ar2 + kc + 8];
            float p00 = __expf(s0.x - m1) * li1, p01 = __expf(s0.y - m1) * li1;
            float p10 = __expf(s1.x - m2) * li2, p11 = __expf(s1.y - m2) * li2;
            float p20 = __expf(s2.x - m1) * li1, p21 = __expf(s2.y - m1) * li1;
            float p30 = __expf(s3.x - m2) * li2, p31 = __expf(s3.y - m2) * li2;
            *(float2*)&attn[ar1 + kc]     = make_float2(p00, p01);
            *(float2*)&attn[ar2 + kc]     = make_float2(p10, p11);
            *(float2*)&attn[ar1 + kc + 8] = make_float2(p20, p21);
            *(float2*)&attn[ar2 + kc + 8] = make_float2(p30, p31);

            uint32_t ah[4], al[4];
            pack_hl2(p00, p01, ah[0], al[0]);
            pack_hl2(p10, p11, ah[1], al[1]);
            pack_hl2(p20, p21, ah[2], al[2]);
            pack_hl2(p30, p31, ah[3], al[3]);

            const int kbo = ks*16*2;
#pragma unroll
            for (int np = 0; np < 4; np++) {
                uint32_t bh4[4], bl4[4];
                ldm_x4(bh4, vho + (np*16*72)*2 + kbo);
                ldm_x4(bl4, vlo + (np*16*72)*2 + kbo);
                mma16816(acc[2*np],   ah, bh4);
                mma16816(acc[2*np],   ah, bl4);
                mma16816(acc[2*np],   al, bh4);
                mma16816(acc[2*np+1], ah, bh4+2);
                mma16816(acc[2*np+1], ah, bl4+2);
                mma16816(acc[2*np+1], al, bh4+2);
            }
        }
        __syncthreads();
    }

    // store O as bf16 hi/lo in (B,N,E)
    const int bb = bh >> 3, hh = bh & 7;
#pragma unroll
    for (int nt = 0; nt < 8; nt++) {
        const int dd = nt*8 + koffb;
        uint32_t hw, lw;
        pack_hl2(acc[nt][0], acc[nt][1], hw, lw);
        size_t b1 = ((size_t)(bb*SEQ + gr1)) * EMB + hh*64 + dd;
        *(uint32_t*)&g_oh[b1] = hw;
        *(uint32_t*)&g_ol[b1] = lw;
        pack_hl2(acc[nt][2], acc[nt][3], hw, lw);
        size_t b2 = ((size_t)(bb*SEQ + gr2)) * EMB + hh*64 + dd;
        *(uint32_t*)&g_oh[b2] = hw;
        *(uint32_t*)&g_ol[b2] = lw;
    }
}

// ---------------------------------------------------------------------------
extern "C" void kernel_launch(void* const* d_in, const int* in_sizes, int n_in,
                              void* d_out, int out_size)
{
    (void)in_sizes; (void)n_in; (void)out_size;
    const float* query = (const float*)d_in[0];
    const float* key_t = (const float*)d_in[1];
    const float* value = (const float*)d_in[2];
    const float* Wq = (const float*)d_in[3];
    const float* bq = (const float*)d_in[4];
    const float* Wk = (const float*)d_in[5];
    const float* bk = (const float*)d_in[6];
    const float* Wv = (const float*)d_in[7];
    const float* bv = (const float*)d_in[8];
    const float* Wo = (const float*)d_in[9];
    const float* bo = (const float*)d_in[10];

    float* out  = (float*)d_out;
    float* attn = out + (size_t)MTOT * EMB;

    cudaFuncSetAttribute(attn_scores_mma,
                         cudaFuncAttributeMaxDynamicSharedMemorySize, S_SMEM_BYTES);

    __nv_bfloat16 *xh, *xl, *wh, *wl;
    cudaGetSymbolAddress((void**)&xh, g_xh);
    cudaGetSymbolAddress((void**)&xl, g_xl);
    cudaGetSymbolAddress((void**)&wh, g_wh);
    cudaGetSymbolAddress((void**)&wl, g_wl);

    dim3 blk(128);
    dim3 gg(MTOT/64, EMB/64);

    const int nx4 = MTOT*EMB/4, nw4 = EMB*EMB/4;

    // Q projection
    cvt_hl_kernel<<<(nx4+255)/256, 256>>>(query, xh, xl, nx4);
    cvt_hl_kernel<<<(nw4+255)/256, 256>>>(Wq, wh, wl, nw4);
    gemm_proj<<<gg, blk>>>(bq, 0.125f, 0, nullptr);   // fold 1/sqrt(D) into Q

    // K projection
    cvt_hl_kernel<<<(nx4+255)/256, 256>>>(key_t, xh, xl, nx4);
    cvt_hl_kernel<<<(nw4+255)/256, 256>>>(Wk, wh, wl, nw4);
    gemm_proj<<<gg, blk>>>(bk, 1.0f, 1, nullptr);

    // V projection (tensor, transpose epilogue)
    cvt_hl_kernel<<<(nx4+255)/256, 256>>>(value, xh, xl, nx4);
    cvt_hl_kernel<<<(nw4+255)/256, 256>>>(Wv, wh, wl, nw4);
    gemm_proj<<<gg, blk>>>(bv, 1.0f, 3, nullptr);

    // attention
    dim3 ga(SEQ/64, BHT);
    attn_scores_mma<<<ga, blk, S_SMEM_BYTES>>>(attn);
    attn_av_mma<<<ga, blk>>>(attn);

    // output projection
    cvt_hl_kernel<<<(nw4+255)/256, 256>>>(Wo, wh, wl, nw4);
    gemm_proj<<<gg, blk>>>(bo, 1.0f, 2, out);
}

// round 11
// speedup vs baseline: 1.6153x; 1.6153x over previous
#include <cuda_runtime.h>
#include <cuda_bf16.h>
#include <cstdint>

// MultiHeadAttention: B=2, N=4096, E=512, H=8, D=64
// Output = concat(flatten(out[B,N,E]), flatten(attn[B,H,N,N]))

#define NH   8
#define HD   64
#define SEQ  4096
#define EMB  512
#define NB   2
#define MTOT (NB * SEQ)   // 8192
#define BHT  (NB * NH)    // 16

// scratch (device globals — allocation inside kernel_launch is forbidden)
__device__ __align__(16) __nv_bfloat16 g_qh[(size_t)BHT * SEQ * HD];
__device__ __align__(16) __nv_bfloat16 g_ql[(size_t)BHT * SEQ * HD];
__device__ __align__(16) __nv_bfloat16 g_kh[(size_t)BHT * SEQ * HD];
__device__ __align__(16) __nv_bfloat16 g_kl[(size_t)BHT * SEQ * HD];
__device__ __align__(16) __nv_bfloat16 g_vth[(size_t)BHT * HD * SEQ];  // V^T: (bh,d,n)
__device__ __align__(16) __nv_bfloat16 g_vtl[(size_t)BHT * HD * SEQ];
__device__ __align__(16) __nv_bfloat16 g_oh[(size_t)MTOT * EMB];       // O: (B,N,E)
__device__ __align__(16) __nv_bfloat16 g_ol[(size_t)MTOT * EMB];
__device__ __align__(16) __nv_bfloat16 g_xh[(size_t)MTOT * EMB];       // staged X hi/lo
__device__ __align__(16) __nv_bfloat16 g_xl[(size_t)MTOT * EMB];
__device__ __align__(16) __nv_bfloat16 g_wh[(size_t)EMB * EMB];        // staged W hi/lo
__device__ __align__(16) __nv_bfloat16 g_wl[(size_t)EMB * EMB];
__device__ float g_m[BHT * SEQ];
__device__ float g_l[BHT * SEQ];

// ===========================================================================
// helpers
// ===========================================================================
__device__ __forceinline__ uint32_t pack2bf16(float lo, float hi) {
    return ((uint32_t)__bfloat16_as_ushort(__float2bfloat16(hi)) << 16) |
           (uint32_t)__bfloat16_as_ushort(__float2bfloat16(lo));
}
__device__ __forceinline__ void split_hl(float x, float& h, float& l) {
    __nv_bfloat16 b = __float2bfloat16(x);
    h = __bfloat162float(b);
    l = x - h;
}
__device__ __forceinline__ void pack_hl2(float a, float b, uint32_t& hw, uint32_t& lw) {
    float ah, al, bh, bl;
    split_hl(a, ah, al);
    split_hl(b, bh, bl);
    hw = pack2bf16(ah, bh);
    lw = pack2bf16(al, bl);
}

__device__ __forceinline__ void mma16816(float* c, const uint32_t* a, const uint32_t* b) {
    asm volatile(
        "mma.sync.aligned.m16n8k16.row.col.f32.bf16.bf16.f32 "
        "{%0,%1,%2,%3}, {%4,%5,%6,%7}, {%8,%9}, {%0,%1,%2,%3};"
        : "+f"(c[0]), "+f"(c[1]), "+f"(c[2]), "+f"(c[3])
        : "r"(a[0]), "r"(a[1]), "r"(a[2]), "r"(a[3]), "r"(b[0]), "r"(b[1]));
}

__device__ __forceinline__ uint32_t smem_u32(const void* p) {
    uint32_t a;
    asm("{ .reg .u64 t; cvta.to.shared.u64 t, %1; cvt.u32.u64 %0, t; }"
        : "=r"(a) : "l"(p));
    return a;
}
__device__ __forceinline__ void cp16(uint32_t dst, const void* src) {
    asm volatile("cp.async.cg.shared.global [%0], [%1], 16;" :: "r"(dst), "l"(src));
}
#define CP_COMMIT() asm volatile("cp.async.commit_group;")
#define CP_WAIT0()  asm volatile("cp.async.wait_group 0;")
#define CP_WAIT1()  asm volatile("cp.async.wait_group 1;")

// ===========================================================================
// fp32 -> bf16 hi/lo conversion (vectorized)
// ===========================================================================
__global__ __launch_bounds__(256) void cvt_hl_kernel(
    const float* __restrict__ src, __nv_bfloat16* __restrict__ h,
    __nv_bfloat16* __restrict__ l, int n4)
{
    int i = blockIdx.x * 256 + threadIdx.x;
    if (i < n4) {
        float4 f = ((const float4*)src)[i];
        uint32_t h01, l01, h23, l23;
        pack_hl2(f.x, f.y, h01, l01);
        pack_hl2(f.z, f.w, h23, l23);
        ((uint2*)h)[i] = make_uint2(h01, h23);
        ((uint2*)l)[i] = make_uint2(l01, l23);
    }
}

// ===========================================================================
// Tensor projection GEMM: C = A @ W^T (+bias, scale) via hi/lo bf16 mma.
// Scalar 32-bit LDS fragment loads (ldmatrix regressed on this part — R10).
// mode 0: Q -> g_qh/g_ql scatter (B,H,N,D), scale=0.125
// mode 1: K -> g_kh/g_kl scatter (B,H,N,D)
// mode 2: out -> fout fp32 (M,E)
// mode 3: V -> g_vth/g_vtl transposed scatter (B,H,D,N)
// CTA 128 thr, tile 64x64, BK=64; warp = 16 rows x 64 cols.
// ===========================================================================
__global__ __launch_bounds__(128) void gemm_proj(
    const float* __restrict__ bias, float scale, int mode,
    float* __restrict__ fout)
{
    __shared__ __align__(16) __nv_bfloat16 sAB[4 * 64 * 72];
    __nv_bfloat16* sAh = sAB;
    __nv_bfloat16* sAl = sAB + 4608;
    __nv_bfloat16* sBh = sAB + 9216;
    __nv_bfloat16* sBl = sAB + 13824;

    const int t = threadIdx.x, w = t >> 5, l = t & 31;
    const int row0 = blockIdx.x * 64, col0 = blockIdx.y * 64;
    const int rA = w*16 + (l >> 2);
    const int koffb = (l & 3) * 2;

    const __nv_bfloat16* Ah = (mode == 2) ? g_oh : g_xh;
    const __nv_bfloat16* Al = (mode == 2) ? g_ol : g_xl;

    float acc[8][4];
#pragma unroll
    for (int nt = 0; nt < 8; nt++)
#pragma unroll
        for (int c = 0; c < 4; c++) acc[nt][c] = 0.f;

    for (int kb = 0; kb < EMB/64; kb++) {
        __syncthreads();
#pragma unroll
        for (int it = 0; it < 4; it++) {
            int j = it*128 + t, row = j >> 3, i = j & 7;
            size_t ga = (size_t)(row0 + row) * EMB + kb*64 + i*8;
            size_t gb = (size_t)(col0 + row) * EMB + kb*64 + i*8;
            *(uint4*)&sAh[row*72 + i*8] = *(const uint4*)(Ah + ga);
            *(uint4*)&sAl[row*72 + i*8] = *(const uint4*)(Al + ga);
            *(uint4*)&sBh[row*72 + i*8] = *(const uint4*)(g_wh + gb);
            *(uint4*)&sBl[row*72 + i*8] = *(const uint4*)(g_wl + gb);
        }
        __syncthreads();

#pragma unroll
        for (int ks = 0; ks < 4; ks++) {
            const int k0 = ks*16 + koffb;
            uint32_t ah[4], al[4];
            ah[0] = *(uint32_t*)&sAh[rA*72     + k0];
            ah[1] = *(uint32_t*)&sAh[(rA+8)*72 + k0];
            ah[2] = *(uint32_t*)&sAh[rA*72     + k0 + 8];
            ah[3] = *(uint32_t*)&sAh[(rA+8)*72 + k0 + 8];
            al[0] = *(uint32_t*)&sAl[rA*72     + k0];
            al[1] = *(uint32_t*)&sAl[(rA+8)*72 + k0];
            al[2] = *(uint32_t*)&sAl[rA*72     + k0 + 8];
            al[3] = *(uint32_t*)&sAl[(rA+8)*72 + k0 + 8];
#pragma unroll
            for (int nt = 0; nt < 8; nt++) {
                const int kr = nt*8 + (l >> 2);
                uint32_t bhf[2], blf[2];
                bhf[0] = *(uint32_t*)&sBh[kr*72 + k0];
                bhf[1] = *(uint32_t*)&sBh[kr*72 + k0 + 8];
                blf[0] = *(uint32_t*)&sBl[kr*72 + k0];
                blf[1] = *(uint32_t*)&sBl[kr*72 + k0 + 8];
                mma16816(acc[nt], ah, bhf);
                mma16816(acc[nt], ah, blf);
                mma16816(acc[nt], al, bhf);
            }
        }
    }

    const int gm1 = row0 + rA, gm2 = gm1 + 8;
    if (mode == 2) {
#pragma unroll
        for (int nt = 0; nt < 8; nt++) {
            const int dd = nt*8 + koffb;
            float b0 = bias[col0 + dd], b1 = bias[col0 + dd + 1];
            *(float2*)&fout[(size_t)gm1*EMB + col0 + dd] =
                make_float2(acc[nt][0] + b0, acc[nt][1] + b1);
            *(float2*)&fout[(size_t)gm2*EMB + col0 + dd] =
                make_float2(acc[nt][2] + b0, acc[nt][3] + b1);
        }
    } else if (mode == 3) {
        // transpose epilogue: stage fp32 into smem, write V^T hi/lo (B,H,D,N)
        float* St = (float*)sAB;   // 64 x 65 floats = 16.6KB < sAh+sAl (18.4KB)
        __syncthreads();
#pragma unroll
        for (int nt = 0; nt < 8; nt++) {
            const int dd = nt*8 + koffb;
            float b0 = bias[col0 + dd], b1 = bias[col0 + dd + 1];
            St[rA*65 + dd]       = acc[nt][0] + b0;
            St[rA*65 + dd + 1]   = acc[nt][1] + b1;
            St[(rA+8)*65 + dd]   = acc[nt][2] + b0;
            St[(rA+8)*65 + dd+1] = acc[nt][3] + b1;
        }
        __syncthreads();
        const int h  = col0 >> 6;
        const int bb = row0 >> 12;
        const int n0 = row0 & (SEQ - 1);
        const int d  = t >> 1;
        const int j0 = (t & 1) * 32;
        uint32_t ph[16], pl[16];
#pragma unroll
        for (int jj = 0; jj < 16; jj++)
            pack_hl2(St[(j0 + 2*jj)*65 + d], St[(j0 + 2*jj + 1)*65 + d], ph[jj], pl[jj]);
        size_t vb = ((size_t)((bb*NH + h)*HD + d)) * SEQ + n0 + j0;
#pragma unroll
        for (int q = 0; q < 4; q++) {
            *(uint4*)&g_vth[vb + q*8] = ((uint4*)ph)[q];
            *(uint4*)&g_vtl[vb + q*8] = ((uint4*)pl)[q];
        }
    } else {
        __nv_bfloat16* oh = (mode == 0) ? g_qh : g_kh;
        __nv_bfloat16* ol = (mode == 0) ? g_ql : g_kl;
        const int h = col0 >> 6;
        const int bb1 = gm1 >> 12, n1 = gm1 & (SEQ-1);
        const int bb2 = gm2 >> 12, n2 = gm2 & (SEQ-1);
#pragma unroll
        for (int nt = 0; nt < 8; nt++) {
            const int dd = nt*8 + koffb;
            float b0 = bias[col0 + dd], b1 = bias[col0 + dd + 1];
            uint32_t hw, lw;
            pack_hl2((acc[nt][0] + b0) * scale, (acc[nt][1] + b1) * scale, hw, lw);
            size_t base1 = ((size_t)((bb1*NH + h)*SEQ + n1)) * HD + dd;
            *(uint32_t*)&oh[base1] = hw;
            *(uint32_t*)&ol[base1] = lw;
            pack_hl2((acc[nt][2] + b0) * scale, (acc[nt][3] + b1) * scale, hw, lw);
            size_t base2 = ((size_t)((bb2*NH + h)*SEQ + n2)) * HD + dd;
            *(uint32_t*)&oh[base2] = hw;
            *(uint32_t*)&ol[base2] = lw;
        }
    }
}

// ===========================================================================
// Scores via mma.sync + cp.async double-buffered K tiles (KT=64).
// CTA = 64 q-rows; 4 warps, warp = 16 rows x 64 keys per iter.
// Scalar 32-bit LDS fragment loads.
// ===========================================================================
#define SOQH 0
#define SOQL 4608
#define SOKH 9216
#define SOKL 18432
#define S_SMEM_BYTES (27648 * 2)

__global__ __launch_bounds__(128) void attn_scores_mma(float* __restrict__ attn)
{
    extern __shared__ __align__(16) __nv_bfloat16 sm[];
    const uint32_t sb = smem_u32(sm);
    const int t = threadIdx.x, w = t >> 5, l = t & 31;
    const int bh = blockIdx.y, q0 = blockIdx.x * 64;

    // Q tile (64 x 64), padded stride 72
#pragma unroll
    for (int it = 0; it < 4; it++) {
        int j = it*128 + t, row = j >> 3, i = j & 7;
        size_t gsrc = ((size_t)(bh*SEQ + q0 + row)) * HD + i*8;
        *(uint4*)&sm[SOQH + row*72 + i*8] = *(const uint4*)(g_qh + gsrc);
        *(uint4*)&sm[SOQL + row*72 + i*8] = *(const uint4*)(g_ql + gsrc);
    }

    const int rA   = w*16 + (l >> 2);
    const int gr1  = q0 + rA, gr2 = gr1 + 8;
    const size_t ar1 = ((size_t)bh*SEQ + gr1) * SEQ;
    const size_t ar2 = ((size_t)bh*SEQ + gr2) * SEQ;
    const int koffb = (l & 3) * 2;

    float m1 = -1e30f, l1 = 0.f, m2 = -1e30f, l2 = 0.f;

    // prefetch K tile 0 into stage 0
    {
#pragma unroll
        for (int it = 0; it < 4; it++) {
            int j = it*128 + t, row = j >> 3, i = j & 7;
            size_t gsrc = ((size_t)(bh*SEQ + row)) * HD + i*8;
            cp16(sb + (SOKH + row*72 + i*8)*2, g_kh + gsrc);
            cp16(sb + (SOKL + row*72 + i*8)*2, g_kl + gsrc);
        }
        CP_COMMIT();
    }

    for (int kt = 0; kt < SEQ/64; kt++) {
        const int cur = kt & 1;
        if (kt + 1 < SEQ/64) {
            const int nxt = cur ^ 1;
#pragma unroll
            for (int it = 0; it < 4; it++) {
                int j = it*128 + t, row = j >> 3, i = j & 7;
                size_t gsrc = ((size_t)(bh*SEQ + (kt+1)*64 + row)) * HD + i*8;
                cp16(sb + (SOKH + nxt*4608 + row*72 + i*8)*2, g_kh + gsrc);
                cp16(sb + (SOKL + nxt*4608 + row*72 + i*8)*2, g_kl + gsrc);
            }
            CP_COMMIT();
            CP_WAIT1();
        } else {
            CP_WAIT0();
        }
        __syncthreads();

        float acc[8][4];
#pragma unroll
        for (int nt = 0; nt < 8; nt++)
#pragma unroll
            for (int c = 0; c < 4; c++) acc[nt][c] = 0.f;

        const int kbase = SOKH + cur*4608;
        const int lbase = SOKL + cur*4608;
#pragma unroll
        for (int ks = 0; ks < 4; ks++) {
            const int k0 = ks*16 + koffb;
            uint32_t ah[4], al[4];
            ah[0] = *(uint32_t*)&sm[SOQH + rA*72     + k0];
            ah[1] = *(uint32_t*)&sm[SOQH + (rA+8)*72 + k0];
            ah[2] = *(uint32_t*)&sm[SOQH + rA*72     + k0 + 8];
            ah[3] = *(uint32_t*)&sm[SOQH + (rA+8)*72 + k0 + 8];
            al[0] = *(uint32_t*)&sm[SOQL + rA*72     + k0];
            al[1] = *(uint32_t*)&sm[SOQL + (rA+8)*72 + k0];
            al[2] = *(uint32_t*)&sm[SOQL + rA*72     + k0 + 8];
            al[3] = *(uint32_t*)&sm[SOQL + (rA+8)*72 + k0 + 8];
#pragma unroll
            for (int nt = 0; nt < 8; nt++) {
                const int kr = nt*8 + (l >> 2);
                uint32_t bhf[2], blf[2];
                bhf[0] = *(uint32_t*)&sm[kbase + kr*72 + k0];
                bhf[1] = *(uint32_t*)&sm[kbase + kr*72 + k0 + 8];
                blf[0] = *(uint32_t*)&sm[lbase + kr*72 + k0];
                blf[1] = *(uint32_t*)&sm[lbase + kr*72 + k0 + 8];
                mma16816(acc[nt], ah, bhf);
                mma16816(acc[nt], ah, blf);
                mma16816(acc[nt], al, bhf);
            }
        }

        // epilogue: store raw scores + online m/l
        float vmax1 = -1e30f, vmax2 = -1e30f;
#pragma unroll
        for (int nt = 0; nt < 8; nt++) {
            vmax1 = fmaxf(vmax1, fmaxf(acc[nt][0], acc[nt][1]));
            vmax2 = fmaxf(vmax2, fmaxf(acc[nt][2], acc[nt][3]));
            const int col = kt*64 + nt*8 + koffb;
            *(float2*)&attn[ar1 + col] = make_float2(acc[nt][0], acc[nt][1]);
            *(float2*)&attn[ar2 + col] = make_float2(acc[nt][2], acc[nt][3]);
        }
        vmax1 = fmaxf(vmax1, __shfl_xor_sync(0xffffffffu, vmax1, 1));
        vmax1 = fmaxf(vmax1, __shfl_xor_sync(0xffffffffu, vmax1, 2));
        vmax2 = fmaxf(vmax2, __shfl_xor_sync(0xffffffffu, vmax2, 1));
        vmax2 = fmaxf(vmax2, __shfl_xor_sync(0xffffffffu, vmax2, 2));

        const float mn1 = fmaxf(m1, vmax1), mn2 = fmaxf(m2, vmax2);
        float es1 = 0.f, es2 = 0.f;
#pragma unroll
        for (int nt = 0; nt < 8; nt++) {
            es1 += __expf(acc[nt][0] - mn1) + __expf(acc[nt][1] - mn1);
            es2 += __expf(acc[nt][2] - mn2) + __expf(acc[nt][3] - mn2);
        }
        es1 += __shfl_xor_sync(0xffffffffu, es1, 1);
        es1 += __shfl_xor_sync(0xffffffffu, es1, 2);
        es2 += __shfl_xor_sync(0xffffffffu, es2, 1);
        es2 += __shfl_xor_sync(0xffffffffu, es2, 2);

        l1 = l1 * __expf(m1 - mn1) + es1;  m1 = mn1;
        l2 = l2 * __expf(m2 - mn2) + es2;  m2 = mn2;

        __syncthreads();
    }

    if ((l & 3) == 0) {
        g_m[bh*SEQ + gr1] = m1;  g_l[bh*SEQ + gr1] = l1;
        g_m[bh*SEQ + gr2] = m2;  g_l[bh*SEQ + gr2] = l2;
    }
}

// ===========================================================================
// AV via mma.sync + cp.async double-buffered V tiles (KT=64): read raw
// scores, normalize, write probs back (final attn), accumulate O = P @ V,
// epilogue stores O as bf16 hi/lo in (B,N,E) for the tensor out-projection.
// Scalar 32-bit LDS fragment loads.
// ===========================================================================
__global__ __launch_bounds__(128) void attn_av_mma(float* __restrict__ attn)
{
    __shared__ __align__(16) __nv_bfloat16 sm[18432];
    const uint32_t sb = smem_u32(sm);
    const int t = threadIdx.x, w = t >> 5, l = t & 31;
    const int bh = blockIdx.y, q0 = blockIdx.x * 64;

    const int rA  = w*16 + (l >> 2);
    const int gr1 = q0 + rA, gr2 = gr1 + 8;
    const size_t ar1 = ((size_t)bh*SEQ + gr1) * SEQ;
    const size_t ar2 = ((size_t)bh*SEQ + gr2) * SEQ;
    const int koffb = (l & 3) * 2;

    const float m1  = g_m[bh*SEQ + gr1];
    const float li1 = 1.0f / g_l[bh*SEQ + gr1];
    const float m2  = g_m[bh*SEQ + gr2];
    const float li2 = 1.0f / g_l[bh*SEQ + gr2];

    float acc[8][4];
#pragma unroll
    for (int nt = 0; nt < 8; nt++)
#pragma unroll
        for (int c = 0; c < 4; c++) acc[nt][c] = 0.f;

    // V stage layout: Vh at stage*4608, Vl at 9216 + stage*4608
    {
#pragma unroll
        for (int it = 0; it < 4; it++) {
            int j = it*128 + t, d = j >> 3, i = j & 7;
            size_t gsrc = ((size_t)(bh*HD + d)) * SEQ + i*8;
            cp16(sb + (d*72 + i*8)*2, g_vth + gsrc);
            cp16(sb + (9216 + d*72 + i*8)*2, g_vtl + gsrc);
        }
        CP_COMMIT();
    }

    for (int kt = 0; kt < SEQ/64; kt++) {
        const int cur = kt & 1;
        if (kt + 1 < SEQ/64) {
            const int nxt = cur ^ 1;
#pragma unroll
            for (int it = 0; it < 4; it++) {
                int j = it*128 + t, d = j >> 3, i = j & 7;
                size_t gsrc = ((size_t)(bh*HD + d)) * SEQ + (kt+1)*64 + i*8;
                cp16(sb + (nxt*4608 + d*72 + i*8)*2, g_vth + gsrc);
                cp16(sb + (9216 + nxt*4608 + d*72 + i*8)*2, g_vtl + gsrc);
            }
            CP_COMMIT();
            CP_WAIT1();
        } else {
            CP_WAIT0();
        }
        __syncthreads();

        const int vh = cur*4608;
        const int vl = 9216 + cur*4608;
#pragma unroll
        for (int ks = 0; ks < 4; ks++) {
            const size_t kc = (size_t)kt*64 + ks*16 + koffb;
            float2 s0 = *(float2*)&attn[ar1 + kc];
            float2 s1 = *(float2*)&attn[ar2 + kc];
            float2 s2 = *(float2*)&attn[ar1 + kc + 8];
            float2 s3 = *(float2*)&attn[ar2 + kc + 8];
            float p00 = __expf(s0.x - m1) * li1, p01 = __expf(s0.y - m1) * li1;
            float p10 = __expf(s1.x - m2) * li2, p11 = __expf(s1.y - m2) * li2;
            float p20 = __expf(s2.x - m1) * li1, p21 = __expf(s2.y - m1) * li1;
            float p30 = __expf(s3.x - m2) * li2, p31 = __expf(s3.y - m2) * li2;
            *(float2*)&attn[ar1 + kc]     = make_float2(p00, p01);
            *(float2*)&attn[ar2 + kc]     = make_float2(p10, p11);
            *(float2*)&attn[ar1 + kc + 8] = make_float2(p20, p21);
            *(float2*)&attn[ar2 + kc + 8] = make_float2(p30, p31);

            uint32_t ah[4], al[4];
            pack_hl2(p00, p01, ah[0], al[0]);
            pack_hl2(p10, p11, ah[1], al[1]);
            pack_hl2(p20, p21, ah[2], al[2]);
            pack_hl2(p30, p31, ah[3], al[3]);

            const int tk0 = ks*16 + koffb;
#pragma unroll
            for (int nt = 0; nt < 8; nt++) {
                const int dd = nt*8 + (l >> 2);
                uint32_t bhf[2], blf[2];
                bhf[0] = *(uint32_t*)&sm[vh + dd*72 + tk0];
                bhf[1] = *(uint32_t*)&sm[vh + dd*72 + tk0 + 8];
                blf[0] = *(uint32_t*)&sm[vl + dd*72 + tk0];
                blf[1] = *(uint32_t*)&sm[vl + dd*72 + tk0 + 8];
                mma16816(acc[nt], ah, bhf);
                mma16816(acc[nt], ah, blf);
                mma16816(acc[nt], al, bhf);
            }
        }
        __syncthreads();
    }

    // store O as bf16 hi/lo in (B,N,E)
    const int bb = bh >> 3, hh = bh & 7;
#pragma unroll
    for (int nt = 0; nt < 8; nt++) {
        const int dd = nt*8 + koffb;
        uint32_t hw, lw;
        pack_hl2(acc[nt][0], acc[nt][1], hw, lw);
        size_t b1 = ((size_t)(bb*SEQ + gr1)) * EMB + hh*64 + dd;
        *(uint32_t*)&g_oh[b1] = hw;
        *(uint32_t*)&g_ol[b1] = lw;
        pack_hl2(acc[nt][2], acc[nt][3], hw, lw);
        size_t b2 = ((size_t)(bb*SEQ + gr2)) * EMB + hh*64 + dd;
        *(uint32_t*)&g_oh[b2] = hw;
        *(uint32_t*)&g_ol[b2] = lw;
    }
}

// ---------------------------------------------------------------------------
extern "C" void kernel_launch(void* const* d_in, const int* in_sizes, int n_in,
                              void* d_out, int out_size)
{
    (void)in_sizes; (void)n_in; (void)out_size;
    const float* query = (const float*)d_in[0];
    const float* key_t = (const float*)d_in[1];
    const float* value = (const float*)d_in[2];
    const float* Wq = (const float*)d_in[3];
    const float* bq = (const float*)d_in[4];
    const float* Wk = (const float*)d_in[5];
    const float* bk = (const float*)d_in[6];
    const float* Wv = (const float*)d_in[7];
    const float* bv = (const float*)d_in[8];
    const float* Wo = (const float*)d_in[9];
    const float* bo = (const float*)d_in[10];

    float* out  = (float*)d_out;
    float* attn = out + (size_t)MTOT * EMB;

    cudaFuncSetAttribute(attn_scores_mma,
                         cudaFuncAttributeMaxDynamicSharedMemorySize, S_SMEM_BYTES);

    __nv_bfloat16 *xh, *xl, *wh, *wl;
    cudaGetSymbolAddress((void**)&xh, g_xh);
    cudaGetSymbolAddress((void**)&xl, g_xl);
    cudaGetSymbolAddress((void**)&wh, g_wh);
    cudaGetSymbolAddress((void**)&wl, g_wl);

    dim3 blk(128);
    dim3 gg(MTOT/64, EMB/64);

    const int nx4 = MTOT*EMB/4, nw4 = EMB*EMB/4;

    // Q projection
    cvt_hl_kernel<<<(nx4+255)/256, 256>>>(query, xh, xl, nx4);
    cvt_hl_kernel<<<(nw4+255)/256, 256>>>(Wq, wh, wl, nw4);
    gemm_proj<<<gg, blk>>>(bq, 0.125f, 0, nullptr);   // fold 1/sqrt(D) into Q

    // K projection
    cvt_hl_kernel<<<(nx4+255)/256, 256>>>(key_t, xh, xl, nx4);
    cvt_hl_kernel<<<(nw4+255)/256, 256>>>(Wk, wh, wl, nw4);
    gemm_proj<<<gg, blk>>>(bk, 1.0f, 1, nullptr);

    // V projection (tensor MMA + transpose epilogue)
    cvt_hl_kernel<<<(nx4+255)/256, 256>>>(value, xh, xl, nx4);
    cvt_hl_kernel<<<(nw4+255)/256, 256>>>(Wv, wh, wl, nw4);
    gemm_proj<<<gg, blk>>>(bv, 1.0f, 3, nullptr);

    // attention
    dim3 ga(SEQ/64, BHT);
    attn_scores_mma<<<ga, blk, S_SMEM_BYTES>>>(attn);
    attn_av_mma<<<ga, blk>>>(attn);

    // output projection
    cvt_hl_kernel<<<(nw4+255)/256, 256>>>(Wo, wh, wl, nw4);
    gemm_proj<<<gg, blk>>>(bo, 1.0f, 2, out);
}

// round 12
// speedup vs baseline: 1.7952x; 1.1113x over previous
#include <cuda_runtime.h>
#include <cuda_bf16.h>
#include <cstdint>

// MultiHeadAttention: B=2, N=4096, E=512, H=8, D=64
// Output = concat(flatten(out[B,N,E]), flatten(attn[B,H,N,N]))

#define NH   8
#define HD   64
#define SEQ  4096
#define EMB  512
#define NB   2
#define MTOT (NB * SEQ)   // 8192
#define BHT  (NB * NH)    // 16

// scratch (device globals — allocation inside kernel_launch is forbidden)
__device__ __align__(16) __nv_bfloat16 g_qh[(size_t)BHT * SEQ * HD];
__device__ __align__(16) __nv_bfloat16 g_ql[(size_t)BHT * SEQ * HD];
__device__ __align__(16) __nv_bfloat16 g_kh[(size_t)BHT * SEQ * HD];
__device__ __align__(16) __nv_bfloat16 g_kl[(size_t)BHT * SEQ * HD];
__device__ __align__(16) __nv_bfloat16 g_vth[(size_t)BHT * HD * SEQ];  // V^T: (bh,d,n)
__device__ __align__(16) __nv_bfloat16 g_vtl[(size_t)BHT * HD * SEQ];
__device__ __align__(16) __nv_bfloat16 g_oh[(size_t)MTOT * EMB];       // O: (B,N,E)
__device__ __align__(16) __nv_bfloat16 g_ol[(size_t)MTOT * EMB];
__device__ __align__(16) __nv_bfloat16 g_xh[(size_t)MTOT * EMB];       // staged X hi/lo
__device__ __align__(16) __nv_bfloat16 g_xl[(size_t)MTOT * EMB];
__device__ __align__(16) __nv_bfloat16 g_wh[(size_t)EMB * EMB];        // staged W hi/lo
__device__ __align__(16) __nv_bfloat16 g_wl[(size_t)EMB * EMB];
__device__ float g_m[BHT * SEQ];
__device__ float g_l[BHT * SEQ];

// ===========================================================================
// helpers
// ===========================================================================
__device__ __forceinline__ uint32_t pack2bf16(float lo, float hi) {
    return ((uint32_t)__bfloat16_as_ushort(__float2bfloat16(hi)) << 16) |
           (uint32_t)__bfloat16_as_ushort(__float2bfloat16(lo));
}
__device__ __forceinline__ void split_hl(float x, float& h, float& l) {
    __nv_bfloat16 b = __float2bfloat16(x);
    h = __bfloat162float(b);
    l = x - h;
}
__device__ __forceinline__ void pack_hl2(float a, float b, uint32_t& hw, uint32_t& lw) {
    float ah, al, bh, bl;
    split_hl(a, ah, al);
    split_hl(b, bh, bl);
    hw = pack2bf16(ah, bh);
    lw = pack2bf16(al, bl);
}

__device__ __forceinline__ void mma16816(float* c, const uint32_t* a, const uint32_t* b) {
    asm volatile(
        "mma.sync.aligned.m16n8k16.row.col.f32.bf16.bf16.f32 "
        "{%0,%1,%2,%3}, {%4,%5,%6,%7}, {%8,%9}, {%0,%1,%2,%3};"
        : "+f"(c[0]), "+f"(c[1]), "+f"(c[2]), "+f"(c[3])
        : "r"(a[0]), "r"(a[1]), "r"(a[2]), "r"(a[3]), "r"(b[0]), "r"(b[1]));
}

__device__ __forceinline__ uint32_t smem_u32(const void* p) {
    uint32_t a;
    asm("{ .reg .u64 t; cvta.to.shared.u64 t, %1; cvt.u32.u64 %0, t; }"
        : "=r"(a) : "l"(p));
    return a;
}
__device__ __forceinline__ void cp16(uint32_t dst, const void* src) {
    asm volatile("cp.async.cg.shared.global [%0], [%1], 16;" :: "r"(dst), "l"(src));
}
#define CP_COMMIT() asm volatile("cp.async.commit_group;")
#define CP_WAIT0()  asm volatile("cp.async.wait_group 0;")
#define CP_WAIT1()  asm volatile("cp.async.wait_group 1;")

// ===========================================================================
// fp32 -> bf16 hi/lo conversion (vectorized)
// ===========================================================================
__global__ __launch_bounds__(256) void cvt_hl_kernel(
    const float* __restrict__ src, __nv_bfloat16* __restrict__ h,
    __nv_bfloat16* __restrict__ l, int n4)
{
    int i = blockIdx.x * 256 + threadIdx.x;
    if (i < n4) {
        float4 f = ((const float4*)src)[i];
        uint32_t h01, l01, h23, l23;
        pack_hl2(f.x, f.y, h01, l01);
        pack_hl2(f.z, f.w, h23, l23);
        ((uint2*)h)[i] = make_uint2(h01, h23);
        ((uint2*)l)[i] = make_uint2(l01, l23);
    }
}

// ===========================================================================
// Tensor projection GEMM: C = A @ W^T (+bias, scale) via hi/lo bf16 mma.
// Scalar 32-bit LDS fragment loads (ldmatrix regressed on this part — R10).
// mode 0: Q -> g_qh/g_ql scatter (B,H,N,D), scale=0.125
// mode 1: K -> g_kh/g_kl scatter (B,H,N,D)
// mode 2: out -> fout fp32 (M,E)
// mode 3: V -> g_vth/g_vtl transposed scatter (B,H,D,N)
// CTA 128 thr, tile 64x64, BK=64; warp = 16 rows x 64 cols.
// ===========================================================================
__global__ __launch_bounds__(128) void gemm_proj(
    const float* __restrict__ bias, float scale, int mode,
    float* __restrict__ fout)
{
    __shared__ __align__(16) __nv_bfloat16 sAB[4 * 64 * 72];
    __nv_bfloat16* sAh = sAB;
    __nv_bfloat16* sAl = sAB + 4608;
    __nv_bfloat16* sBh = sAB + 9216;
    __nv_bfloat16* sBl = sAB + 13824;

    const int t = threadIdx.x, w = t >> 5, l = t & 31;
    const int row0 = blockIdx.x * 64, col0 = blockIdx.y * 64;
    const int rA = w*16 + (l >> 2);
    const int koffb = (l & 3) * 2;

    const __nv_bfloat16* Ah = (mode == 2) ? g_oh : g_xh;
    const __nv_bfloat16* Al = (mode == 2) ? g_ol : g_xl;

    float acc[8][4];
#pragma unroll
    for (int nt = 0; nt < 8; nt++)
#pragma unroll
        for (int c = 0; c < 4; c++) acc[nt][c] = 0.f;

    for (int kb = 0; kb < EMB/64; kb++) {
        __syncthreads();
#pragma unroll
        for (int it = 0; it < 4; it++) {
            int j = it*128 + t, row = j >> 3, i = j & 7;
            size_t ga = (size_t)(row0 + row) * EMB + kb*64 + i*8;
            size_t gb = (size_t)(col0 + row) * EMB + kb*64 + i*8;
            *(uint4*)&sAh[row*72 + i*8] = *(const uint4*)(Ah + ga);
            *(uint4*)&sAl[row*72 + i*8] = *(const uint4*)(Al + ga);
            *(uint4*)&sBh[row*72 + i*8] = *(const uint4*)(g_wh + gb);
            *(uint4*)&sBl[row*72 + i*8] = *(const uint4*)(g_wl + gb);
        }
        __syncthreads();

#pragma unroll
        for (int ks = 0; ks < 4; ks++) {
            const int k0 = ks*16 + koffb;
            uint32_t ah[4], al[4];
            ah[0] = *(uint32_t*)&sAh[rA*72     + k0];
            ah[1] = *(uint32_t*)&sAh[(rA+8)*72 + k0];
            ah[2] = *(uint32_t*)&sAh[rA*72     + k0 + 8];
            ah[3] = *(uint32_t*)&sAh[(rA+8)*72 + k0 + 8];
            al[0] = *(uint32_t*)&sAl[rA*72     + k0];
            al[1] = *(uint32_t*)&sAl[(rA+8)*72 + k0];
            al[2] = *(uint32_t*)&sAl[rA*72     + k0 + 8];
            al[3] = *(uint32_t*)&sAl[(rA+8)*72 + k0 + 8];
#pragma unroll
            for (int nt = 0; nt < 8; nt++) {
                const int kr = nt*8 + (l >> 2);
                uint32_t bhf[2], blf[2];
                bhf[0] = *(uint32_t*)&sBh[kr*72 + k0];
                bhf[1] = *(uint32_t*)&sBh[kr*72 + k0 + 8];
                blf[0] = *(uint32_t*)&sBl[kr*72 + k0];
                blf[1] = *(uint32_t*)&sBl[kr*72 + k0 + 8];
                mma16816(acc[nt], ah, bhf);
                mma16816(acc[nt], ah, blf);
                mma16816(acc[nt], al, bhf);
            }
        }
    }

    const int gm1 = row0 + rA, gm2 = gm1 + 8;
    if (mode == 2) {
#pragma unroll
        for (int nt = 0; nt < 8; nt++) {
            const int dd = nt*8 + koffb;
            float b0 = bias[col0 + dd], b1 = bias[col0 + dd + 1];
            *(float2*)&fout[(size_t)gm1*EMB + col0 + dd] =
                make_float2(acc[nt][0] + b0, acc[nt][1] + b1);
            *(float2*)&fout[(size_t)gm2*EMB + col0 + dd] =
                make_float2(acc[nt][2] + b0, acc[nt][3] + b1);
        }
    } else if (mode == 3) {
        // transpose epilogue: stage fp32 into smem, write V^T hi/lo (B,H,D,N)
        float* St = (float*)sAB;   // 64 x 65 floats = 16.6KB < sAh+sAl (18.4KB)
        __syncthreads();
#pragma unroll
        for (int nt = 0; nt < 8; nt++) {
            const int dd = nt*8 + koffb;
            float b0 = bias[col0 + dd], b1 = bias[col0 + dd + 1];
            St[rA*65 + dd]       = acc[nt][0] + b0;
            St[rA*65 + dd + 1]   = acc[nt][1] + b1;
            St[(rA+8)*65 + dd]   = acc[nt][2] + b0;
            St[(rA+8)*65 + dd+1] = acc[nt][3] + b1;
        }
        __syncthreads();
        const int h  = col0 >> 6;
        const int bb = row0 >> 12;
        const int n0 = row0 & (SEQ - 1);
        const int d  = t >> 1;
        const int j0 = (t & 1) * 32;
        uint32_t ph[16], pl[16];
#pragma unroll
        for (int jj = 0; jj < 16; jj++)
            pack_hl2(St[(j0 + 2*jj)*65 + d], St[(j0 + 2*jj + 1)*65 + d], ph[jj], pl[jj]);
        size_t vb = ((size_t)((bb*NH + h)*HD + d)) * SEQ + n0 + j0;
#pragma unroll
        for (int q = 0; q < 4; q++) {
            *(uint4*)&g_vth[vb + q*8] = ((uint4*)ph)[q];
            *(uint4*)&g_vtl[vb + q*8] = ((uint4*)pl)[q];
        }
    } else {
        __nv_bfloat16* oh = (mode == 0) ? g_qh : g_kh;
        __nv_bfloat16* ol = (mode == 0) ? g_ql : g_kl;
        const int h = col0 >> 6;
        const int bb1 = gm1 >> 12, n1 = gm1 & (SEQ-1);
        const int bb2 = gm2 >> 12, n2 = gm2 & (SEQ-1);
#pragma unroll
        for (int nt = 0; nt < 8; nt++) {
            const int dd = nt*8 + koffb;
            float b0 = bias[col0 + dd], b1 = bias[col0 + dd + 1];
            uint32_t hw, lw;
            pack_hl2((acc[nt][0] + b0) * scale, (acc[nt][1] + b1) * scale, hw, lw);
            size_t base1 = ((size_t)((bb1*NH + h)*SEQ + n1)) * HD + dd;
            *(uint32_t*)&oh[base1] = hw;
            *(uint32_t*)&ol[base1] = lw;
            pack_hl2((acc[nt][2] + b0) * scale, (acc[nt][3] + b1) * scale, hw, lw);
            size_t base2 = ((size_t)((bb2*NH + h)*SEQ + n2)) * HD + dd;
            *(uint32_t*)&oh[base2] = hw;
            *(uint32_t*)&ol[base2] = lw;
        }
    }
}

// ===========================================================================
// Scores via mma.sync + cp.async double-buffered K tiles (KT=64).
// CTA = 128 q-rows; 4 warps, warp = 32 rows (2 m16 tiles) x 64 keys.
// B-fragments reused across both m-tiles: 48 MMA per 48 LDS per ks.
// SMEM elems: Qh[9216] Ql[9216] Kh 2x4608 Kl 2x4608 = 73728B dyn.
// ===========================================================================
#define SOQH 0
#define SOQL 9216
#define SOKH 18432
#define SOKL 27648
#define S_SMEM_BYTES (36864 * 2)

__global__ __launch_bounds__(128) void attn_scores_mma(float* __restrict__ attn)
{
    extern __shared__ __align__(16) __nv_bfloat16 sm[];
    const uint32_t sb = smem_u32(sm);
    const int t = threadIdx.x, w = t >> 5, l = t & 31;
    const int bh = blockIdx.y, q0 = blockIdx.x * 128;

    // Q tile (128 x 64), padded stride 72
#pragma unroll
    for (int it = 0; it < 8; it++) {
        int j = it*128 + t, row = j >> 3, i = j & 7;
        size_t gsrc = ((size_t)(bh*SEQ + q0 + row)) * HD + i*8;
        *(uint4*)&sm[SOQH + row*72 + i*8] = *(const uint4*)(g_qh + gsrc);
        *(uint4*)&sm[SOQL + row*72 + i*8] = *(const uint4*)(g_ql + gsrc);
    }

    const int rq   = l >> 2;             // quad row 0..7
    const int rb0  = w*32;               // warp row base
    // rows handled by this thread: gr[0..3] = q0+rb0+rq, +8, +16, +24
    const int koffb = (l & 3) * 2;
    size_t ar[4];
#pragma unroll
    for (int r = 0; r < 4; r++)
        ar[r] = ((size_t)bh*SEQ + (q0 + rb0 + rq + r*8)) * SEQ;

    float mr[4], ls[4];
#pragma unroll
    for (int r = 0; r < 4; r++) { mr[r] = -1e30f; ls[r] = 0.f; }

    // prefetch K tile 0 into stage 0
    {
#pragma unroll
        for (int it = 0; it < 4; it++) {
            int j = it*128 + t, row = j >> 3, i = j & 7;
            size_t gsrc = ((size_t)(bh*SEQ + row)) * HD + i*8;
            cp16(sb + (SOKH + row*72 + i*8)*2, g_kh + gsrc);
            cp16(sb + (SOKL + row*72 + i*8)*2, g_kl + gsrc);
        }
        CP_COMMIT();
    }

    for (int kt = 0; kt < SEQ/64; kt++) {
        const int cur = kt & 1;
        if (kt + 1 < SEQ/64) {
            const int nxt = cur ^ 1;
#pragma unroll
            for (int it = 0; it < 4; it++) {
                int j = it*128 + t, row = j >> 3, i = j & 7;
                size_t gsrc = ((size_t)(bh*SEQ + (kt+1)*64 + row)) * HD + i*8;
                cp16(sb + (SOKH + nxt*4608 + row*72 + i*8)*2, g_kh + gsrc);
                cp16(sb + (SOKL + nxt*4608 + row*72 + i*8)*2, g_kl + gsrc);
            }
            CP_COMMIT();
            CP_WAIT1();
        } else {
            CP_WAIT0();
        }
        __syncthreads();

        float acc[2][8][4];
#pragma unroll
        for (int mt = 0; mt < 2; mt++)
#pragma unroll
            for (int nt = 0; nt < 8; nt++)
#pragma unroll
                for (int c = 0; c < 4; c++) acc[mt][nt][c] = 0.f;

        const int kbase = SOKH + cur*4608;
        const int lbase = SOKL + cur*4608;
#pragma unroll
        for (int ks = 0; ks < 4; ks++) {
            const int k0 = ks*16 + koffb;
            uint32_t ah0[4], al0[4], ah1[4], al1[4];
            {
                const int r0 = rb0 + rq;
                ah0[0] = *(uint32_t*)&sm[SOQH + r0*72      + k0];
                ah0[1] = *(uint32_t*)&sm[SOQH + (r0+8)*72  + k0];
                ah0[2] = *(uint32_t*)&sm[SOQH + r0*72      + k0 + 8];
                ah0[3] = *(uint32_t*)&sm[SOQH + (r0+8)*72  + k0 + 8];
                al0[0] = *(uint32_t*)&sm[SOQL + r0*72      + k0];
                al0[1] = *(uint32_t*)&sm[SOQL + (r0+8)*72  + k0];
                al0[2] = *(uint32_t*)&sm[SOQL + r0*72      + k0 + 8];
                al0[3] = *(uint32_t*)&sm[SOQL + (r0+8)*72  + k0 + 8];
                const int r1 = r0 + 16;
                ah1[0] = *(uint32_t*)&sm[SOQH + r1*72      + k0];
                ah1[1] = *(uint32_t*)&sm[SOQH + (r1+8)*72  + k0];
                ah1[2] = *(uint32_t*)&sm[SOQH + r1*72      + k0 + 8];
                ah1[3] = *(uint32_t*)&sm[SOQH + (r1+8)*72  + k0 + 8];
                al1[0] = *(uint32_t*)&sm[SOQL + r1*72      + k0];
                al1[1] = *(uint32_t*)&sm[SOQL + (r1+8)*72  + k0];
                al1[2] = *(uint32_t*)&sm[SOQL + r1*72      + k0 + 8];
                al1[3] = *(uint32_t*)&sm[SOQL + (r1+8)*72  + k0 + 8];
            }
#pragma unroll
            for (int nt = 0; nt < 8; nt++) {
                const int kr = nt*8 + rq;
                uint32_t bhf[2], blf[2];
                bhf[0] = *(uint32_t*)&sm[kbase + kr*72 + k0];
                bhf[1] = *(uint32_t*)&sm[kbase + kr*72 + k0 + 8];
                blf[0] = *(uint32_t*)&sm[lbase + kr*72 + k0];
                blf[1] = *(uint32_t*)&sm[lbase + kr*72 + k0 + 8];
                mma16816(acc[0][nt], ah0, bhf);
                mma16816(acc[0][nt], ah0, blf);
                mma16816(acc[0][nt], al0, bhf);
                mma16816(acc[1][nt], ah1, bhf);
                mma16816(acc[1][nt], ah1, blf);
                mma16816(acc[1][nt], al1, bhf);
            }
        }

        // epilogue: store raw scores + online m/l (4 rows per thread)
#pragma unroll
        for (int mt = 0; mt < 2; mt++) {
            float vA = -1e30f, vB = -1e30f;
#pragma unroll
            for (int nt = 0; nt < 8; nt++) {
                vA = fmaxf(vA, fmaxf(acc[mt][nt][0], acc[mt][nt][1]));
                vB = fmaxf(vB, fmaxf(acc[mt][nt][2], acc[mt][nt][3]));
                const int col = kt*64 + nt*8 + koffb;
                *(float2*)&attn[ar[2*mt]   + col] = make_float2(acc[mt][nt][0], acc[mt][nt][1]);
                *(float2*)&attn[ar[2*mt+1] + col] = make_float2(acc[mt][nt][2], acc[mt][nt][3]);
            }
            vA = fmaxf(vA, __shfl_xor_sync(0xffffffffu, vA, 1));
            vA = fmaxf(vA, __shfl_xor_sync(0xffffffffu, vA, 2));
            vB = fmaxf(vB, __shfl_xor_sync(0xffffffffu, vB, 1));
            vB = fmaxf(vB, __shfl_xor_sync(0xffffffffu, vB, 2));

            const float mnA = fmaxf(mr[2*mt], vA), mnB = fmaxf(mr[2*mt+1], vB);
            float eA = 0.f, eB = 0.f;
#pragma unroll
            for (int nt = 0; nt < 8; nt++) {
                eA += __expf(acc[mt][nt][0] - mnA) + __expf(acc[mt][nt][1] - mnA);
                eB += __expf(acc[mt][nt][2] - mnB) + __expf(acc[mt][nt][3] - mnB);
            }
            eA += __shfl_xor_sync(0xffffffffu, eA, 1);
            eA += __shfl_xor_sync(0xffffffffu, eA, 2);
            eB += __shfl_xor_sync(0xffffffffu, eB, 1);
            eB += __shfl_xor_sync(0xffffffffu, eB, 2);

            ls[2*mt]   = ls[2*mt]   * __expf(mr[2*mt]   - mnA) + eA;  mr[2*mt]   = mnA;
            ls[2*mt+1] = ls[2*mt+1] * __expf(mr[2*mt+1] - mnB) + eB;  mr[2*mt+1] = mnB;
        }

        __syncthreads();
    }

    if ((l & 3) == 0) {
#pragma unroll
        for (int r = 0; r < 4; r++) {
            const int grow = q0 + rb0 + rq + r*8;
            g_m[bh*SEQ + grow] = mr[r];
            g_l[bh*SEQ + grow] = ls[r];
        }
    }
}

// ===========================================================================
// AV via mma.sync + cp.async double-buffered V tiles (KT=64).
// CTA = 128 q-rows; warp = 32 rows x 64 d. Reads raw scores, normalizes,
// writes probs back (final attn), O = P @ V, stores O bf16 hi/lo in (B,N,E).
// SMEM: Vh 2x4608, Vl 2x4608 = 36864B static.
// ===========================================================================
__global__ __launch_bounds__(128) void attn_av_mma(float* __restrict__ attn)
{
    __shared__ __align__(16) __nv_bfloat16 sm[18432];
    const uint32_t sb = smem_u32(sm);
    const int t = threadIdx.x, w = t >> 5, l = t & 31;
    const int bh = blockIdx.y, q0 = blockIdx.x * 128;

    const int rq  = l >> 2;
    const int rb0 = w*32;
    const int koffb = (l & 3) * 2;

    size_t ar[4];
    float mv[4], li[4];
#pragma unroll
    for (int r = 0; r < 4; r++) {
        const int grow = q0 + rb0 + rq + r*8;
        ar[r] = ((size_t)bh*SEQ + grow) * SEQ;
        mv[r] = g_m[bh*SEQ + grow];
        li[r] = 1.0f / g_l[bh*SEQ + grow];
    }

    float acc[2][8][4];
#pragma unroll
    for (int mt = 0; mt < 2; mt++)
#pragma unroll
        for (int nt = 0; nt < 8; nt++)
#pragma unroll
            for (int c = 0; c < 4; c++) acc[mt][nt][c] = 0.f;

    // V stage layout: Vh at stage*4608, Vl at 9216 + stage*4608
    {
#pragma unroll
        for (int it = 0; it < 4; it++) {
            int j = it*128 + t, d = j >> 3, i = j & 7;
            size_t gsrc = ((size_t)(bh*HD + d)) * SEQ + i*8;
            cp16(sb + (d*72 + i*8)*2, g_vth + gsrc);
            cp16(sb + (9216 + d*72 + i*8)*2, g_vtl + gsrc);
        }
        CP_COMMIT();
    }

    for (int kt = 0; kt < SEQ/64; kt++) {
        const int cur = kt & 1;
        if (kt + 1 < SEQ/64) {
            const int nxt = cur ^ 1;
#pragma unroll
            for (int it = 0; it < 4; it++) {
                int j = it*128 + t, d = j >> 3, i = j & 7;
                size_t gsrc = ((size_t)(bh*HD + d)) * SEQ + (kt+1)*64 + i*8;
                cp16(sb + (nxt*4608 + d*72 + i*8)*2, g_vth + gsrc);
                cp16(sb + (9216 + nxt*4608 + d*72 + i*8)*2, g_vtl + gsrc);
            }
            CP_COMMIT();
            CP_WAIT1();
        } else {
            CP_WAIT0();
        }
        __syncthreads();

        const int vh = cur*4608;
        const int vl = 9216 + cur*4608;
#pragma unroll
        for (int ks = 0; ks < 4; ks++) {
            const size_t kc = (size_t)kt*64 + ks*16 + koffb;
            uint32_t ah0[4], al0[4], ah1[4], al1[4];
#pragma unroll
            for (int mt = 0; mt < 2; mt++) {
                float2 s0 = *(float2*)&attn[ar[2*mt]   + kc];
                float2 s1 = *(float2*)&attn[ar[2*mt+1] + kc];
                float2 s2 = *(float2*)&attn[ar[2*mt]   + kc + 8];
                float2 s3 = *(float2*)&attn[ar[2*mt+1] + kc + 8];
                const float mA = mv[2*mt],  lA = li[2*mt];
                const float mB = mv[2*mt+1], lB = li[2*mt+1];
                float p00 = __expf(s0.x - mA) * lA, p01 = __expf(s0.y - mA) * lA;
                float p10 = __expf(s1.x - mB) * lB, p11 = __expf(s1.y - mB) * lB;
                float p20 = __expf(s2.x - mA) * lA, p21 = __expf(s2.y - mA) * lA;
                float p30 = __expf(s3.x - mB) * lB, p31 = __expf(s3.y - mB) * lB;
                *(float2*)&attn[ar[2*mt]   + kc]     = make_float2(p00, p01);
                *(float2*)&attn[ar[2*mt+1] + kc]     = make_float2(p10, p11);
                *(float2*)&attn[ar[2*mt]   + kc + 8] = make_float2(p20, p21);
                *(float2*)&attn[ar[2*mt+1] + kc + 8] = make_float2(p30, p31);
                uint32_t* ah = mt ? ah1 : ah0;
                uint32_t* al = mt ? al1 : al0;
                pack_hl2(p00, p01, ah[0], al[0]);
                pack_hl2(p10, p11, ah[1], al[1]);
                pack_hl2(p20, p21, ah[2], al[2]);
                pack_hl2(p30, p31, ah[3], al[3]);
            }

            const int tk0 = ks*16 + koffb;
#pragma unroll
            for (int nt = 0; nt < 8; nt++) {
                const int dd = nt*8 + rq;
                uint32_t bhf[2], blf[2];
                bhf[0] = *(uint32_t*)&sm[vh + dd*72 + tk0];
                bhf[1] = *(uint32_t*)&sm[vh + dd*72 + tk0 + 8];
                blf[0] = *(uint32_t*)&sm[vl + dd*72 + tk0];
                blf[1] = *(uint32_t*)&sm[vl + dd*72 + tk0 + 8];
                mma16816(acc[0][nt], ah0, bhf);
                mma16816(acc[0][nt], ah0, blf);
                mma16816(acc[0][nt], al0, bhf);
                mma16816(acc[1][nt], ah1, bhf);
                mma16816(acc[1][nt], ah1, blf);
                mma16816(acc[1][nt], al1, bhf);
            }
        }
        __syncthreads();
    }

    // store O as bf16 hi/lo in (B,N,E)
    const int bb = bh >> 3, hh = bh & 7;
#pragma unroll
    for (int mt = 0; mt < 2; mt++)
#pragma unroll
        for (int nt = 0; nt < 8; nt++) {
            const int dd = nt*8 + koffb;
            const int gr1 = q0 + rb0 + rq + (2*mt)*8;
            const int gr2 = gr1 + 8;
            uint32_t hw, lw;
            pack_hl2(acc[mt][nt][0], acc[mt][nt][1], hw, lw);
            size_t b1 = ((size_t)(bb*SEQ + gr1)) * EMB + hh*64 + dd;
            *(uint32_t*)&g_oh[b1] = hw;
            *(uint32_t*)&g_ol[b1] = lw;
            pack_hl2(acc[mt][nt][2], acc[mt][nt][3], hw, lw);
            size_t b2 = ((size_t)(bb*SEQ + gr2)) * EMB + hh*64 + dd;
            *(uint32_t*)&g_oh[b2] = hw;
            *(uint32_t*)&g_ol[b2] = lw;
        }
}

// ---------------------------------------------------------------------------
extern "C" void kernel_launch(void* const* d_in, const int* in_sizes, int n_in,
                              void* d_out, int out_size)
{
    (void)in_sizes; (void)n_in; (void)out_size;
    const float* query = (const float*)d_in[0];
    const float* key_t = (const float*)d_in[1];
    const float* value = (const float*)d_in[2];
    const float* Wq = (const float*)d_in[3];
    const float* bq = (const float*)d_in[4];
    const float* Wk = (const float*)d_in[5];
    const float* bk = (const float*)d_in[6];
    const float* Wv = (const float*)d_in[7];
    const float* bv = (const float*)d_in[8];
    const float* Wo = (const float*)d_in[9];
    const float* bo = (const float*)d_in[10];

    float* out  = (float*)d_out;
    float* attn = out + (size_t)MTOT * EMB;

    cudaFuncSetAttribute(attn_scores_mma,
                         cudaFuncAttributeMaxDynamicSharedMemorySize, S_SMEM_BYTES);

    __nv_bfloat16 *xh, *xl, *wh, *wl;
    cudaGetSymbolAddress((void**)&xh, g_xh);
    cudaGetSymbolAddress((void**)&xl, g_xl);
    cudaGetSymbolAddress((void**)&wh, g_wh);
    cudaGetSymbolAddress((void**)&wl, g_wl);

    dim3 blk(128);
    dim3 gg(MTOT/64, EMB/64);

    const int nx4 = MTOT*EMB/4, nw4 = EMB*EMB/4;

    // Q projection
    cvt_hl_kernel<<<(nx4+255)/256, 256>>>(query, xh, xl, nx4);
    cvt_hl_kernel<<<(nw4+255)/256, 256>>>(Wq, wh, wl, nw4);
    gemm_proj<<<gg, blk>>>(bq, 0.125f, 0, nullptr);   // fold 1/sqrt(D) into Q

    // K projection
    cvt_hl_kernel<<<(nx4+255)/256, 256>>>(key_t, xh, xl, nx4);
    cvt_hl_kernel<<<(nw4+255)/256, 256>>>(Wk, wh, wl, nw4);
    gemm_proj<<<gg, blk>>>(bk, 1.0f, 1, nullptr);

    // V projection (tensor MMA + transpose epilogue)
    cvt_hl_kernel<<<(nx4+255)/256, 256>>>(value, xh, xl, nx4);
    cvt_hl_kernel<<<(nw4+255)/256, 256>>>(Wv, wh, wl, nw4);
    gemm_proj<<<gg, blk>>>(bv, 1.0f, 3, nullptr);

    // attention (CTA = 128 q-rows)
    dim3 ga(SEQ/128, BHT);
    attn_scores_mma<<<ga, blk, S_SMEM_BYTES>>>(attn);
    attn_av_mma<<<ga, blk>>>(attn);

    // output projection
    cvt_hl_kernel<<<(nw4+255)/256, 256>>>(Wo, wh, wl, nw4);
    gemm_proj<<<gg, blk>>>(bo, 1.0f, 2, out);
}